// round 15
// baseline (speedup 1.0000x reference)
#include <cuda_runtime.h>
#include <cuda_fp16.h>

// (B,C,D,H,W) = (4,8,16,256,256), k=3, stride=1, pad=1
#define BC   32
#define DD   16
#define HH   256
#define WW   256
#define HW   (HH*WW)
#define CHV  (DD*HW)

#define TH     16             // tile height (= #warps)
#define TWPIX  64             // tile width in pixels (2 px / lane)
#define ROWS   (TH+2)         // 18
#define COLS   68             // col1 = w0-1 halo, cols2..65 data, col66 = w0+64 halo
#define TS     (ROWS*COLS)    // 1224
#define NPAIRS (TS/2)         // 612
#define PPR    (COLS/2)       // 34 pairs per row
#define NT     (TH*32)        // 512

__device__ __forceinline__ __half2 u2h(unsigned int u) {
    return *reinterpret_cast<__half2*>(&u);
}
__device__ __forceinline__ unsigned int h2u(__half2 h) {
    return *reinterpret_cast<unsigned int*>(&h);
}

__global__ void __launch_bounds__(NT, 2)
softargmax_kernel(const float* __restrict__ x, float* __restrict__ out)
{
    const int bc = blockIdx.z;
    const int h0 = blockIdx.y * TH;
    const int w0 = blockIdx.x * TWPIX;
    const int tid = threadIdx.x;
    const int tx = tid & 31;
    const int ty = tid >> 5;

    // double-buffered half2(e, e*x) slice tiles
    __shared__ __align__(16) __half2 tile[2][TS];

    const float* __restrict__ xc = x + (size_t)bc * CHV;

    // ---- paired fill: 2 slots cover 612 pairs (slot1: tid<100) ----
    int  base[2], offB[2];
    bool vA[2], vB[2], v2[2], inp[2];
    #pragma unroll
    for (int j = 0; j < 2; j++) {
        int P = tid + j * NT;
        inp[j] = (P < NPAIRS);
        int r  = P / PPR;
        int c0 = 2 * (P % PPR);
        int hh = h0 + r - 1;
        bool hok = inp[j] && (hh >= 0) && (hh < HH);
        int wwA = w0 + c0 - 2;
        int wwB = wwA + 1;
        vA[j] = hok && (c0 >= 2) && (c0 <= 66) && (wwA >= 0) && (wwA < WW);
        vB[j] = hok && (c0 + 1 <= 66) && (wwB >= 0) && (wwB < WW);
        v2[j] = vA[j] && vB[j];
        base[j] = vA[j] ? hh * WW + wwA : 0;
        offB[j] = vB[j] ? hh * WW + wwB : 0;
    }

    float ra[2], rb[2];

    #define LOADSLICE(ptr)                                                    \
        _Pragma("unroll")                                                     \
        for (int j = 0; j < 2; j++) {                                         \
            ra[j] = 0.f; rb[j] = 0.f;                                         \
            if (v2[j]) {                                                      \
                float2 t = __ldg(reinterpret_cast<const float2*>((ptr) + base[j])); \
                ra[j] = t.x; rb[j] = t.y;                                     \
            } else {                                                          \
                if (vA[j]) ra[j] = __ldg((ptr) + base[j]);                    \
                if (vB[j]) rb[j] = __ldg((ptr) + offB[j]);                    \
            }                                                                 \
        }

    #define PUBLISH(BUF)                                                      \
        _Pragma("unroll")                                                     \
        for (int j = 0; j < 2; j++) {                                         \
            if (inp[j]) {                                                     \
                float eA = vA[j] ? __expf(ra[j]) : 0.f;                       \
                float eB = vB[j] ? __expf(rb[j]) : 0.f;                       \
                uint2 val = make_uint2(                                       \
                    h2u(__floats2half2_rn(eA, eA * ra[j])),                   \
                    h2u(__floats2half2_rn(eB, eB * rb[j])));                  \
                *reinterpret_cast<uint2*>(&tile[BUF][2 * (tid + j * NT)]) = val; \
            }                                                                 \
        }

    // Separable 3x3: vertical reduce (colsum, ydiff) then horizontal stencil.
    // s[0]=(Σe,Σv) px0  s[1]=xnum px0  s[2]=ynum px0 ; s[3..5] px1
    #define ACCUM(s, BUF)                                                     \
        do {                                                                  \
            const int rbase = (ty) * COLS + 2 + 2 * tx;                       \
            const uint2 u0 = *reinterpret_cast<const uint2*>(&tile[BUF][rbase]); \
            const uint2 u1 = *reinterpret_cast<const uint2*>(                 \
                &tile[BUF][rbase + COLS]);                                    \
            const uint2 u2 = *reinterpret_cast<const uint2*>(                 \
                &tile[BUF][rbase + 2 * COLS]);                                \
            const __half2 a0 = u2h(u0.x), a1 = u2h(u1.x), a2 = u2h(u2.x);     \
            const __half2 b0 = u2h(u0.y), b1 = u2h(u1.y), b2 = u2h(u2.y);     \
            __half2 cs0 = __hadd2(__hadd2(a0, a1), a2);                       \
            __half2 cs1 = __hadd2(__hadd2(b0, b1), b2);                       \
            __half2 yd0 = __hsub2(a2, a0);                                    \
            __half2 yd1 = __hsub2(b2, b0);                                    \
            __half2 csL, csR, ydL, ydR;                                       \
            {                                                                 \
                unsigned int t1, t2, t3, t4;                                  \
                t1 = __shfl_up_sync(0xFFFFFFFFu,                              \
                        *reinterpret_cast<unsigned int*>(&cs1), 1);           \
                t2 = __shfl_down_sync(0xFFFFFFFFu,                            \
                        *reinterpret_cast<unsigned int*>(&cs0), 1);           \
                t3 = __shfl_up_sync(0xFFFFFFFFu,                              \
                        *reinterpret_cast<unsigned int*>(&yd1), 1);           \
                t4 = __shfl_down_sync(0xFFFFFFFFu,                            \
                        *reinterpret_cast<unsigned int*>(&yd0), 1);           \
                csL = u2h(t1); csR = u2h(t2); ydL = u2h(t3); ydR = u2h(t4);   \
            }                                                                 \
            if (tx == 0) {                                                    \
                const int hb = (ty) * COLS + 1;                               \
                const __half2 g0 = tile[BUF][hb];                             \
                const __half2 g1 = tile[BUF][hb + COLS];                      \
                const __half2 g2 = tile[BUF][hb + 2 * COLS];                  \
                csL = __hadd2(__hadd2(g0, g1), g2);                           \
                ydL = __hsub2(g2, g0);                                        \
            }                                                                 \
            if (tx == 31) {                                                   \
                const int hb = (ty) * COLS + 66;                              \
                const __half2 g0 = tile[BUF][hb];                             \
                const __half2 g1 = tile[BUF][hb + COLS];                      \
                const __half2 g2 = tile[BUF][hb + 2 * COLS];                  \
                csR = __hadd2(__hadd2(g0, g1), g2);                           \
                ydR = __hsub2(g2, g0);                                        \
            }                                                                 \
            const __half2 t = __hadd2(cs0, cs1);                              \
            (s)[0] = __hadd2(csL, t);                                         \
            (s)[3] = __hadd2(t, csR);                                         \
            (s)[1] = __hsub2(cs1, csL);                                       \
            (s)[4] = __hsub2(csR, cs0);                                       \
            const __half2 ty2 = __hadd2(yd0, yd1);                            \
            (s)[2] = __hadd2(ydL, ty2);                                       \
            (s)[5] = __hadd2(ty2, ydR);                                       \
        } while (0)

    const __half2 zero = __floats2half2_rn(0.f, 0.f);
    __half2 p[6], c[6], n[6];
    #pragma unroll
    for (int k = 0; k < 6; k++) p[k] = zero;

    // prologue: slice 0 -> buf0
    LOADSLICE(xc);
    PUBLISH(0);
    LOADSLICE(xc + HW);                         // prefetch slice 1
    __syncthreads();
    ACCUM(c, 0);

    const float hf = (float)(h0 + ty);
    const float wf = (float)(w0 + 2 * tx);
    const size_t pixbase = (size_t)(h0 + ty) * WW + (w0 + 2 * tx);
    float* pcoord = out + (size_t)bc * 3 * CHV + pixbase;
    float* pval   = out + (size_t)BC * 3 * CHV + (size_t)bc * CHV + pixbase;

    #pragma unroll
    for (int d = 0; d < DD; d++) {
        if (d + 1 < DD) {
            const int buf = (d + 1) & 1;
            PUBLISH(buf);                       // slice d+1
            if (d + 2 < DD) {                   // prefetch slice d+2
                LOADSLICE(xc + (size_t)(d + 2) * HW);
            }
            __syncthreads();                    // one barrier per slice
            ACCUM(n, buf);
        } else {
            #pragma unroll
            for (int k = 0; k < 6; k++) n[k] = zero;
        }

        const __half2 tot0 = __hadd2(__hadd2(p[0], c[0]), n[0]);
        const __half2 tot1 = __hadd2(__hadd2(p[3], c[3]), n[3]);
        const float inv0 = __fdividef(1.0f, __low2float(tot0) + 1e-8f);
        const float inv1 = __fdividef(1.0f, __low2float(tot1) + 1e-8f);
        const float df = (float)d;

        float2 z2 = make_float2(
            df + __low2float(__hsub2(n[0], p[0])) * inv0,
            df + __low2float(__hsub2(n[3], p[3])) * inv1);
        float2 x2 = make_float2(
            wf       + __low2float(__hadd2(__hadd2(p[1], c[1]), n[1])) * inv0,
            wf + 1.f + __low2float(__hadd2(__hadd2(p[4], c[4]), n[4])) * inv1);
        float2 y2 = make_float2(
            hf + __low2float(__hadd2(__hadd2(p[2], c[2]), n[2])) * inv0,
            hf + __low2float(__hadd2(__hadd2(p[5], c[5]), n[5])) * inv1);
        float2 v2 = make_float2(__high2float(tot0) * inv0,
                                __high2float(tot1) * inv1);

        __stcs(reinterpret_cast<float2*>(pcoord),           z2);
        __stcs(reinterpret_cast<float2*>(pcoord + CHV),     x2);
        __stcs(reinterpret_cast<float2*>(pcoord + 2 * CHV), y2);
        __stcs(reinterpret_cast<float2*>(pval),             v2);

        pcoord += HW;
        pval   += HW;

        #pragma unroll
        for (int k = 0; k < 6; k++) { p[k] = c[k]; c[k] = n[k]; }
    }
}

extern "C" void kernel_launch(void* const* d_in, const int* in_sizes, int n_in,
                              void* d_out, int out_size) {
    const float* x = (const float*)d_in[0];
    float* out = (float*)d_out;
    softargmax_kernel<<<dim3(WW / TWPIX, HH / TH, BC), NT>>>(x, out);
}

// round 16
// speedup vs baseline: 1.0048x; 1.0048x over previous
#include <cuda_runtime.h>
#include <cuda_fp16.h>

// (B,C,D,H,W) = (4,8,16,256,256), k=3, stride=1, pad=1
#define BC   32
#define DD   16
#define HH   256
#define WW   256
#define HW   (HH*WW)
#define CHV  (DD*HW)

#define TH     16             // tile height (= #warps)
#define TWPIX  64             // tile width in pixels (2 px / lane)
#define ROWS   (TH+2)         // 18
#define COLS   68             // col1 = w0-1 halo, cols2..65 data, col66 = w0+64 halo
#define TS     (ROWS*COLS)    // 1224
#define NPAIRS (TS/2)         // 612
#define PPR    (COLS/2)       // 34 pairs per row
#define NT     (TH*32)        // 512

__device__ __forceinline__ __half2 u2h(unsigned int u) {
    return *reinterpret_cast<__half2*>(&u);
}
__device__ __forceinline__ unsigned int h2u(__half2 h) {
    return *reinterpret_cast<unsigned int*>(&h);
}

__global__ void __launch_bounds__(NT, 2)
softargmax_kernel(const float* __restrict__ x, float* __restrict__ out)
{
    const int bc = blockIdx.z;
    const int h0 = blockIdx.y * TH;
    const int w0 = blockIdx.x * TWPIX;
    const int tid = threadIdx.x;
    const int tx = tid & 31;
    const int ty = tid >> 5;

    // double-buffered half2(e, e*x) slice tiles
    __shared__ __align__(16) __half2 tile[2][TS];

    const float* __restrict__ xc = x + (size_t)bc * CHV;

    // ---- paired fill: 2 slots cover 612 pairs (slot1: tid<100) ----
    int  base[2], offB[2];
    bool vA[2], vB[2], v2[2], inp[2];
    #pragma unroll
    for (int j = 0; j < 2; j++) {
        int P = tid + j * NT;
        inp[j] = (P < NPAIRS);
        int r  = P / PPR;
        int c0 = 2 * (P % PPR);
        int hh = h0 + r - 1;
        bool hok = inp[j] && (hh >= 0) && (hh < HH);
        int wwA = w0 + c0 - 2;
        int wwB = wwA + 1;
        vA[j] = hok && (c0 >= 2) && (c0 <= 66) && (wwA >= 0) && (wwA < WW);
        vB[j] = hok && (c0 + 1 <= 66) && (wwB >= 0) && (wwB < WW);
        v2[j] = vA[j] && vB[j];
        base[j] = vA[j] ? hh * WW + wwA : 0;
        offB[j] = vB[j] ? hh * WW + wwB : 0;
    }

    float ra[2], rb[2];

    #define LOADSLICE(ptr)                                                    \
        _Pragma("unroll")                                                     \
        for (int j = 0; j < 2; j++) {                                         \
            ra[j] = 0.f; rb[j] = 0.f;                                         \
            if (v2[j]) {                                                      \
                float2 t = __ldg(reinterpret_cast<const float2*>((ptr) + base[j])); \
                ra[j] = t.x; rb[j] = t.y;                                     \
            } else {                                                          \
                if (vA[j]) ra[j] = __ldg((ptr) + base[j]);                    \
                if (vB[j]) rb[j] = __ldg((ptr) + offB[j]);                    \
            }                                                                 \
        }

    #define PUBLISH(BUF)                                                      \
        _Pragma("unroll")                                                     \
        for (int j = 0; j < 2; j++) {                                         \
            if (inp[j]) {                                                     \
                float eA = vA[j] ? __expf(ra[j]) : 0.f;                       \
                float eB = vB[j] ? __expf(rb[j]) : 0.f;                       \
                uint2 val = make_uint2(                                       \
                    h2u(__floats2half2_rn(eA, eA * ra[j])),                   \
                    h2u(__floats2half2_rn(eB, eB * rb[j])));                  \
                *reinterpret_cast<uint2*>(&tile[BUF][2 * (tid + j * NT)]) = val; \
            }                                                                 \
        }

    // Separable 3x3: vertical reduce (colsum, ydiff) then horizontal stencil.
    // s[0]=(Σe,Σv) px0  s[1]=xnum px0  s[2]=ynum px0 ; s[3..5] px1
    #define ACCUM(s, BUF)                                                     \
        do {                                                                  \
            const int rbase = (ty) * COLS + 2 + 2 * tx;                       \
            const uint2 u0 = *reinterpret_cast<const uint2*>(&tile[BUF][rbase]); \
            const uint2 u1 = *reinterpret_cast<const uint2*>(                 \
                &tile[BUF][rbase + COLS]);                                    \
            const uint2 u2 = *reinterpret_cast<const uint2*>(                 \
                &tile[BUF][rbase + 2 * COLS]);                                \
            const __half2 a0 = u2h(u0.x), a1 = u2h(u1.x), a2 = u2h(u2.x);     \
            const __half2 b0 = u2h(u0.y), b1 = u2h(u1.y), b2 = u2h(u2.y);     \
            __half2 cs0 = __hadd2(__hadd2(a0, a1), a2);                       \
            __half2 cs1 = __hadd2(__hadd2(b0, b1), b2);                       \
            __half2 yd0 = __hsub2(a2, a0);                                    \
            __half2 yd1 = __hsub2(b2, b0);                                    \
            __half2 csL, csR, ydL, ydR;                                       \
            {                                                                 \
                unsigned int t1, t2, t3, t4;                                  \
                t1 = __shfl_up_sync(0xFFFFFFFFu,                              \
                        *reinterpret_cast<unsigned int*>(&cs1), 1);           \
                t2 = __shfl_down_sync(0xFFFFFFFFu,                            \
                        *reinterpret_cast<unsigned int*>(&cs0), 1);           \
                t3 = __shfl_up_sync(0xFFFFFFFFu,                              \
                        *reinterpret_cast<unsigned int*>(&yd1), 1);           \
                t4 = __shfl_down_sync(0xFFFFFFFFu,                            \
                        *reinterpret_cast<unsigned int*>(&yd0), 1);           \
                csL = u2h(t1); csR = u2h(t2); ydL = u2h(t3); ydR = u2h(t4);   \
            }                                                                 \
            if (tx == 0) {                                                    \
                const int hb = (ty) * COLS + 1;                               \
                const __half2 g0 = tile[BUF][hb];                             \
                const __half2 g1 = tile[BUF][hb + COLS];                      \
                const __half2 g2 = tile[BUF][hb + 2 * COLS];                  \
                csL = __hadd2(__hadd2(g0, g1), g2);                           \
                ydL = __hsub2(g2, g0);                                        \
            }                                                                 \
            if (tx == 31) {                                                   \
                const int hb = (ty) * COLS + 66;                              \
                const __half2 g0 = tile[BUF][hb];                             \
                const __half2 g1 = tile[BUF][hb + COLS];                      \
                const __half2 g2 = tile[BUF][hb + 2 * COLS];                  \
                csR = __hadd2(__hadd2(g0, g1), g2);                           \
                ydR = __hsub2(g2, g0);                                        \
            }                                                                 \
            const __half2 t = __hadd2(cs0, cs1);                              \
            (s)[0] = __hadd2(csL, t);                                         \
            (s)[3] = __hadd2(t, csR);                                         \
            (s)[1] = __hsub2(cs1, csL);                                       \
            (s)[4] = __hsub2(csR, cs0);                                       \
            const __half2 ty2 = __hadd2(yd0, yd1);                            \
            (s)[2] = __hadd2(ydL, ty2);                                       \
            (s)[5] = __hadd2(ty2, ydR);                                       \
        } while (0)

    const __half2 zero = __floats2half2_rn(0.f, 0.f);
    __half2 p[6], c[6], n[6];
    #pragma unroll
    for (int k = 0; k < 6; k++) p[k] = zero;

    // prologue: slice 0 -> buf0
    LOADSLICE(xc);
    PUBLISH(0);
    LOADSLICE(xc + HW);                         // prefetch slice 1
    __syncthreads();
    ACCUM(c, 0);

    const float hf = (float)(h0 + ty);
    const float wf = (float)(w0 + 2 * tx);
    const size_t pixbase = (size_t)(h0 + ty) * WW + (w0 + 2 * tx);
    float* pcoord = out + (size_t)bc * 3 * CHV + pixbase;
    float* pval   = out + (size_t)BC * 3 * CHV + (size_t)bc * CHV + pixbase;

    #pragma unroll
    for (int d = 0; d < DD; d++) {
        if (d + 1 < DD) {
            const int buf = (d + 1) & 1;
            PUBLISH(buf);                       // slice d+1
            if (d + 2 < DD) {                   // prefetch slice d+2
                LOADSLICE(xc + (size_t)(d + 2) * HW);
            }
            __syncthreads();                    // one barrier per slice
            ACCUM(n, buf);
        } else {
            #pragma unroll
            for (int k = 0; k < 6; k++) n[k] = zero;
        }

        const __half2 tot0 = __hadd2(__hadd2(p[0], c[0]), n[0]);
        const __half2 tot1 = __hadd2(__hadd2(p[3], c[3]), n[3]);
        const float inv0 = __fdividef(1.0f, __low2float(tot0) + 1e-8f);
        const float inv1 = __fdividef(1.0f, __low2float(tot1) + 1e-8f);
        const float df = (float)d;

        float2 z2 = make_float2(
            df + __low2float(__hsub2(n[0], p[0])) * inv0,
            df + __low2float(__hsub2(n[3], p[3])) * inv1);
        float2 x2 = make_float2(
            wf       + __low2float(__hadd2(__hadd2(p[1], c[1]), n[1])) * inv0,
            wf + 1.f + __low2float(__hadd2(__hadd2(p[4], c[4]), n[4])) * inv1);
        float2 y2 = make_float2(
            hf + __low2float(__hadd2(__hadd2(p[2], c[2]), n[2])) * inv0,
            hf + __low2float(__hadd2(__hadd2(p[5], c[5]), n[5])) * inv1);
        float2 v2 = make_float2(__high2float(tot0) * inv0,
                                __high2float(tot1) * inv1);

        __stcs(reinterpret_cast<float2*>(pcoord),           z2);
        __stcs(reinterpret_cast<float2*>(pcoord + CHV),     x2);
        __stcs(reinterpret_cast<float2*>(pcoord + 2 * CHV), y2);
        __stcs(reinterpret_cast<float2*>(pval),             v2);

        pcoord += HW;
        pval   += HW;

        #pragma unroll
        for (int k = 0; k < 6; k++) { p[k] = c[k]; c[k] = n[k]; }
    }
}

extern "C" void kernel_launch(void* const* d_in, const int* in_sizes, int n_in,
                              void* d_out, int out_size) {
    const float* x = (const float*)d_in[0];
    float* out = (float*)d_out;
    softargmax_kernel<<<dim3(WW / TWPIX, HH / TH, BC), NT>>>(x, out);
}